// round 7
// baseline (speedup 1.0000x reference)
#include <cuda_runtime.h>
#include <cuda_bf16.h>
#include <math.h>

// Problem constants
#define Bq    4
#define CH_G  64
#define Hh    240
#define Ww    320
#define HW    (Hh*Ww)          // 76800
#define NUM   8
#define C_FEA 8
#define COUT  24
#define HIN   120
#define WIN   160
#define QW    (HW/8)           // 9600

// Scratch (device globals; no runtime allocation allowed)
__device__ __align__(16) float g_oaT[(size_t)Bq*HW*COUT];      // conv output, pixel-major (29.5 MB)
__device__ __align__(16) float g_feaC[(size_t)Bq*C_FEA*HW];    // upsampled fea, channel-major (9.8 MB)
__device__ __align__(16) float g_cw[(size_t)Bq*HW*NUM];        // cos_w, pixel-major (9.8 MB)

#define FFMA2(d,a,b,c_) asm("fma.rn.f32x2 %0, %1, %2, %3;" : "=l"(d) : "l"(a), "l"(b), "l"(c_))
#define DUP2(d,s)       asm("mov.b64 %0, {%1, %1};" : "=l"(d) : "f"(s))

// ---------------------------------------------------------------------------
// Stage 1: 2x bilinear upsample (jax.image.resize "bilinear": half-pixel
// centers -> weights {0.75,0.25}, edge renorm == index clamp).
// Output CHANNEL-MAJOR: g_feaC[b][c][i][j].
// ---------------------------------------------------------------------------
__global__ void upsample_kernel(const float* __restrict__ fea) {
    int t = blockIdx.x * 256 + threadIdx.x;
    if (t >= Bq * HW) return;
    int b = t / HW; int pix = t - b * HW;
    int i = pix / Ww; int j = pix - i * Ww;

    int ky = i >> 1;
    int y1 = (i & 1) ? min(ky + 1, HIN - 1) : max(ky - 1, 0);
    int kx = j >> 1;
    int x1 = (j & 1) ? min(kx + 1, WIN - 1) : max(kx - 1, 0);
    const float wm = 0.75f, ws = 0.25f;

#pragma unroll
    for (int c = 0; c < C_FEA; c++) {
        const float* fp = fea + ((size_t)(b * C_FEA + c)) * (HIN * WIN);
        float v00 = fp[ky * WIN + kx];
        float v01 = fp[ky * WIN + x1];
        float v10 = fp[y1 * WIN + kx];
        float v11 = fp[y1 * WIN + x1];
        g_feaC[((size_t)(b * C_FEA + c)) * HW + pix] =
            wm * (wm * v00 + ws * v01) + ws * (wm * v10 + ws * v11);
    }
}

// ---------------------------------------------------------------------------
// Stage 2: 3x3 conv, 64 -> 24 channels, pad 1, + bias. FFMA2 (fma.rn.f32x2)
// with output channels paired: 12 f32x2 accumulators. One pixel per thread,
// 256-thread blocks (proven R6 configuration). Output pixel-major.
// ---------------------------------------------------------------------------
__global__ __launch_bounds__(256) void conv_kernel(const float* __restrict__ gin,
                                                   const float* __restrict__ wgt,
                                                   const float* __restrict__ bias) {
    __shared__ __align__(16) float sg[16 * 10 * 34];   // 16ch x (8+2) x (32+2)
    __shared__ __align__(16) float sw[16 * 9 * 24];    // [c][k][o]

    int tx = threadIdx.x & 31, ty = threadIdx.x >> 5;
    int bx = blockIdx.x * 32, by = blockIdx.y * 8, b = blockIdx.z;

    unsigned long long acc[12];
#pragma unroll
    for (int q = 0; q < 12; q++) {
        float b0 = bias[2 * q], b1 = bias[2 * q + 1];
        asm("mov.b64 %0, {%1, %2};" : "=l"(acc[q]) : "f"(b0), "f"(b1));
    }

    for (int cc = 0; cc < 4; cc++) {
        __syncthreads();
        // load guidance tile (with zero pad halo)
        for (int idx = threadIdx.x; idx < 16 * 340; idx += 256) {
            int c = idx / 340; int r = idx - c * 340;
            int yy = r / 34;   int xx = r - yy * 34;
            int gy = by + yy - 1, gx = bx + xx - 1;
            float v = 0.f;
            if (gy >= 0 && gy < Hh && gx >= 0 && gx < Ww)
                v = gin[((size_t)(b * CH_G + cc * 16 + c)) * HW + gy * Ww + gx];
            sg[idx] = v;
        }
        // load weight chunk, layout [c][k][o]
        for (int idx = threadIdx.x; idx < 16 * 216; idx += 256) {
            int c = idx / 216; int r = idx - c * 216;
            int k = r / 24;    int o = r - k * 24;
            sw[idx] = wgt[((size_t)o * CH_G + cc * 16 + c) * 9 + k];
        }
        __syncthreads();

        for (int c = 0; c < 16; c++) {
            unsigned long long gd[9];
#pragma unroll
            for (int dy = 0; dy < 3; dy++)
#pragma unroll
                for (int dx = 0; dx < 3; dx++) {
                    float gv = sg[c * 340 + (ty + dy) * 34 + (tx + dx)];
                    DUP2(gd[dy * 3 + dx], gv);
                }
#pragma unroll
            for (int k = 0; k < 9; k++) {
                const ulonglong2* wv = (const ulonglong2*)&sw[(c * 9 + k) * 24];
                unsigned long long gk = gd[k];
#pragma unroll
                for (int h = 0; h < 6; h++) {
                    ulonglong2 w2 = wv[h];
                    FFMA2(acc[2 * h],     w2.x, gk, acc[2 * h]);
                    FFMA2(acc[2 * h + 1], w2.y, gk, acc[2 * h + 1]);
                }
            }
        }
    }

    int gy = by + ty, gx = bx + tx;
    size_t pix = (size_t)gy * Ww + gx;
    ulonglong2* dst = (ulonglong2*)&g_oaT[((size_t)b * HW + pix) * COUT];
#pragma unroll
    for (int h = 0; h < 6; h++)
        dst[h] = make_ulonglong2(acc[2 * h], acc[2 * h + 1]);
}

// ---------------------------------------------------------------------------
// Stage 3: fused deformable-sample + scramble-reduce (cos_w), one thread per
// output pixel pd.  Math validated in R4:
//   ch = pd/9600 (uniform per pd), q = pd%9600, pix2 = 8q+a (a=0..7),
//   cos_w[n](pd) = sum_a fw[a] * S_ch(pix2, n)
// where fw[a] = fea_up[channel a](pd)  and  S_ch(pix2,n) = bilinear (zero
// pad) of fea_up channel ch at x = oa[2n](pix2)+base, y = oa[2n+1](pix2)+base,
// base = i2 for n<4 else j2.  Single-channel taps over CHANNEL-MAJOR fea ->
// sector-efficient, L2-resident (300KB/channel). Writes g_cw coalesced.
// ---------------------------------------------------------------------------
__global__ __launch_bounds__(256) void cw_kernel() {
    int t = blockIdx.x * 256 + threadIdx.x;   // exact grid: Bq*HW
    int b = t / HW; int pd = t - b * HW;
    int ch = pd / QW; int q = pd - ch * QW;

    // fw[a] = fea channel a at pd (coalesced per a)
    const float* fC = g_feaC + (size_t)b * C_FEA * HW;
    float fw[8];
#pragma unroll
    for (int a = 0; a < 8; a++) fw[a] = fC[(size_t)a * HW + pd];

    const float* chp = fC + (size_t)ch * HW;   // single channel plane for taps
    const float* oaB = g_oaT + (size_t)b * HW * COUT;

    int pix2b = q * 8;                 // 8 | Ww: all 8 sample pixels share a row
    int i2 = pix2b / Ww;
    int j2b = pix2b - i2 * Ww;
    float fi2 = (float)i2;

    float cosw[8] = {0, 0, 0, 0, 0, 0, 0, 0};

#pragma unroll
    for (int a = 0; a < 8; a++) {
        int pix2 = pix2b + a;
        // 16 offset floats for pix2
        float of[16];
        {
            const float4* op = (const float4*)(oaB + (size_t)pix2 * COUT);
            float4 o0 = op[0], o1 = op[1], o2 = op[2], o3 = op[3];
            of[0] = o0.x;  of[1] = o0.y;  of[2]  = o0.z;  of[3]  = o0.w;
            of[4] = o1.x;  of[5] = o1.y;  of[6]  = o1.z;  of[7]  = o1.w;
            of[8] = o2.x;  of[9] = o2.y;  of[10] = o2.z;  of[11] = o2.w;
            of[12] = o3.x; of[13] = o3.y; of[14] = o3.z;  of[15] = o3.w;
        }
        float fj2 = (float)(j2b + a);
        float fa = fw[a];
#pragma unroll
        for (int n = 0; n < 8; n++) {
            float base = (n < 4) ? fi2 : fj2;
            float x = of[2 * n] + base;
            float y = of[2 * n + 1] + base;

            float x0 = floorf(x), y0 = floorf(y);
            float fx = x - x0, fy = y - y0;
            float s = 0.f;
#pragma unroll
            for (int cy = 0; cy < 2; cy++)
#pragma unroll
                for (int cx = 0; cx < 2; cx++) {
                    float xi = x0 + cx, yi = y0 + cy;
                    if (xi >= 0.f && xi <= (float)(Ww - 1) && yi >= 0.f && yi <= (float)(Hh - 1)) {
                        float wb = (cy ? fy : 1.f - fy) * (cx ? fx : 1.f - fx);
                        s += wb * chp[(int)yi * Ww + (int)xi];
                    }
                }
            cosw[n] += fa * s;
        }
    }

    float4* cwv = (float4*)&g_cw[(size_t)t * NUM];
    cwv[0] = make_float4(cosw[0], cosw[1], cosw[2], cosw[3]);
    cwv[1] = make_float4(cosw[4], cosw[5], cosw[6], cosw[7]);
}

// single-channel bilinear with zero padding (reference _bilinear_zeros)
__device__ __forceinline__ float bil1(const float* __restrict__ img, float x, float y) {
    float x0 = floorf(x), y0 = floorf(y);
    float fx = x - x0, fy = y - y0;
    float r = 0.f;
#pragma unroll
    for (int cy = 0; cy < 2; cy++) {
#pragma unroll
        for (int cx = 0; cx < 2; cx++) {
            float xi = x0 + cx, yi = y0 + cy;
            if (xi >= 0.f && xi <= (float)(Ww - 1) && yi >= 0.f && yi <= (float)(Hh - 1)) {
                float wgt = (cy ? fy : 1.f - fy) * (cx ? fx : 1.f - fx);
                r += wgt * img[(int)yi * Ww + (int)xi];
            }
        }
    }
    return r;
}

// ---------------------------------------------------------------------------
// Stage 4: epilogue (R4-measured 22.7us variant). Reads oaT (6 x LDG.128) and
// cw (2 x LDG.128); TGASS tanh scaling, confidence bilinear on gt_depth_conf,
// abs-sum clamp normalize, reference channel insert, softmax, both outputs.
// ---------------------------------------------------------------------------
__global__ void final_kernel(const float* __restrict__ gt,
                             const float* __restrict__ ascp,
                             float* __restrict__ out) {
    int t = blockIdx.x * 256 + threadIdx.x;
    if (t >= Bq * HW) return;
    int b = t / HW; int pix = t - b * HW;
    int i = pix / Ww; int j = pix - i * Ww;

    float o[COUT];
    {
        const float4* ov = (const float4*)&g_oaT[(size_t)t * COUT];
#pragma unroll
        for (int h = 0; h < 6; h++) {
            float4 v = ov[h];
            o[4 * h + 0] = v.x; o[4 * h + 1] = v.y;
            o[4 * h + 2] = v.z; o[4 * h + 3] = v.w;
        }
    }
    float cosw[8];
    {
        const float4* cv = (const float4*)&g_cw[(size_t)t * NUM];
        float4 c0 = cv[0], c1 = cv[1];
        cosw[0] = c0.x; cosw[1] = c0.y; cosw[2] = c0.z; cosw[3] = c0.w;
        cosw[4] = c1.x; cosw[5] = c1.y; cosw[6] = c1.z; cosw[7] = c1.w;
    }

    float denom = ascp[0] + 1e-8f;
    const float* gb = gt + (size_t)b * HW;

    float aff[8];
#pragma unroll
    for (int n = 0; n < 8; n++) {
        float a0 = tanhf(o[16 + n] * cosw[n]) / denom;
        float y = o[2 * n]     + (float)i;   // channel 0 = dy
        float x = o[2 * n + 1] + (float)j;   // channel 1 = dx
        aff[n] = a0 * bil1(gb, x, y);
    }

    float sabs = 0.f;
#pragma unroll
    for (int n = 0; n < 8; n++) sabs += fabsf(aff[n]);
    sabs += 1e-4f;
    sabs = fmaxf(sabs, 1.0f);

    float ssum = 0.f;
#pragma unroll
    for (int n = 0; n < 8; n++) { aff[n] = aff[n] / sabs; ssum += aff[n]; }

    float v[9];
    v[0] = aff[0]; v[1] = aff[1]; v[2] = aff[2]; v[3] = aff[3];
    v[4] = 1.0f - ssum;
    v[5] = aff[4]; v[6] = aff[5]; v[7] = aff[6]; v[8] = aff[7];

    float m = v[0];
#pragma unroll
    for (int k = 1; k < 9; k++) m = fmaxf(m, v[k]);
    float e[9], es = 0.f;
#pragma unroll
    for (int k = 0; k < 9; k++) { e[k] = expf(v[k] - m); es += e[k]; }
    float inv = 1.0f / es;

    // output: offset_full (B,18,H,W) flattened, then aff_full (B,9,H,W)
    const size_t OFFA = (size_t)Bq * 18 * HW;
#pragma unroll
    for (int k = 0; k < 8; k++)
        out[((size_t)(b * 18 + k)) * HW + pix] = o[k];
    out[((size_t)(b * 18 + 8)) * HW + pix] = 0.f;
    out[((size_t)(b * 18 + 9)) * HW + pix] = 0.f;
#pragma unroll
    for (int k = 10; k < 18; k++)
        out[((size_t)(b * 18 + k)) * HW + pix] = o[k - 2];
#pragma unroll
    for (int k = 0; k < 9; k++)
        out[OFFA + ((size_t)(b * 9 + k)) * HW + pix] = e[k] * inv;
}

// ---------------------------------------------------------------------------
extern "C" void kernel_launch(void* const* d_in, const int* in_sizes, int n_in,
                              void* d_out, int out_size) {
    const float* guidance = (const float*)d_in[0];
    const float* gt       = (const float*)d_in[1];
    const float* fea      = (const float*)d_in[2];
    const float* conv_w   = (const float*)d_in[3];
    const float* conv_b   = (const float*)d_in[4];
    const float* asc      = (const float*)d_in[5];
    float* out = (float*)d_out;

    upsample_kernel<<<(Bq * HW + 255) / 256, 256>>>(fea);

    dim3 cg(Ww / 32, Hh / 8, Bq);   // 10 x 30 x 4 = 1200 blocks, 256 threads
    conv_kernel<<<cg, 256>>>(guidance, conv_w, conv_b);

    cw_kernel<<<(Bq * HW) / 256, 256>>>();       // 1200 blocks exact

    final_kernel<<<(Bq * HW + 255) / 256, 256>>>(gt, asc, out);
}

// round 8
// speedup vs baseline: 1.1019x; 1.1019x over previous
#include <cuda_runtime.h>
#include <cuda_bf16.h>
#include <math.h>

// Problem constants
#define Bq    4
#define CH_G  64
#define Hh    240
#define Ww    320
#define HW    (Hh*Ww)          // 76800
#define NUM   8
#define C_FEA 8
#define COUT  24
#define HIN   120
#define WIN   160
#define Pn    (HW*NUM)         // 614400

// Scratch (device globals; no runtime allocation allowed)
__device__ __align__(16) float g_oaT[(size_t)Bq*HW*COUT];      // conv output, pixel-major (29.5 MB)
__device__ __align__(16) float g_feaT[(size_t)Bq*HW*C_FEA];    // upsampled fea, channel-last (9.8 MB)
__device__ __align__(16) float g_smp[(size_t)Bq*C_FEA*Pn];     // sampled tensor (78.6 MB)

#define FFMA2(d,a,b,c_) asm("fma.rn.f32x2 %0, %1, %2, %3;" : "=l"(d) : "l"(a), "l"(b), "l"(c_))
#define DUP2(d,s)       asm("mov.b64 %0, {%1, %1};" : "=l"(d) : "f"(s))

// ---------------------------------------------------------------------------
// Stage 1: 2x bilinear upsample (jax.image.resize "bilinear": half-pixel
// centers -> weights {0.75,0.25}, edge renorm == index clamp).
// Output channel-last: g_feaT[b][i][j][c].
// ---------------------------------------------------------------------------
__global__ void upsample_kernel(const float* __restrict__ fea) {
    int t = blockIdx.x * 256 + threadIdx.x;
    if (t >= Bq * HW) return;
    int b = t / HW; int pix = t - b * HW;
    int i = pix / Ww; int j = pix - i * Ww;

    int ky = i >> 1;
    int y1 = (i & 1) ? min(ky + 1, HIN - 1) : max(ky - 1, 0);
    int kx = j >> 1;
    int x1 = (j & 1) ? min(kx + 1, WIN - 1) : max(kx - 1, 0);
    const float wm = 0.75f, ws = 0.25f;

    float* dst = &g_feaT[(size_t)t * C_FEA];
#pragma unroll
    for (int c = 0; c < C_FEA; c++) {
        const float* fp = fea + ((size_t)(b * C_FEA + c)) * (HIN * WIN);
        float v00 = fp[ky * WIN + kx];
        float v01 = fp[ky * WIN + x1];
        float v10 = fp[y1 * WIN + kx];
        float v11 = fp[y1 * WIN + x1];
        dst[c] = wm * (wm * v00 + ws * v01) + ws * (wm * v10 + ws * v11);
    }
}

// ---------------------------------------------------------------------------
// Stage 2: 3x3 conv, 64 -> 24 channels, pad 1, + bias. FFMA2 (fma.rn.f32x2)
// with output channels paired: 12 f32x2 accumulators. One pixel per thread,
// 256-thread blocks (proven R6 configuration). Output pixel-major.
// ---------------------------------------------------------------------------
__global__ __launch_bounds__(256) void conv_kernel(const float* __restrict__ gin,
                                                   const float* __restrict__ wgt,
                                                   const float* __restrict__ bias) {
    __shared__ __align__(16) float sg[16 * 10 * 34];   // 16ch x (8+2) x (32+2)
    __shared__ __align__(16) float sw[16 * 9 * 24];    // [c][k][o]

    int tx = threadIdx.x & 31, ty = threadIdx.x >> 5;
    int bx = blockIdx.x * 32, by = blockIdx.y * 8, b = blockIdx.z;

    unsigned long long acc[12];
#pragma unroll
    for (int q = 0; q < 12; q++) {
        float b0 = bias[2 * q], b1 = bias[2 * q + 1];
        asm("mov.b64 %0, {%1, %2};" : "=l"(acc[q]) : "f"(b0), "f"(b1));
    }

    for (int cc = 0; cc < 4; cc++) {
        __syncthreads();
        // load guidance tile (with zero pad halo)
        for (int idx = threadIdx.x; idx < 16 * 340; idx += 256) {
            int c = idx / 340; int r = idx - c * 340;
            int yy = r / 34;   int xx = r - yy * 34;
            int gy = by + yy - 1, gx = bx + xx - 1;
            float v = 0.f;
            if (gy >= 0 && gy < Hh && gx >= 0 && gx < Ww)
                v = gin[((size_t)(b * CH_G + cc * 16 + c)) * HW + gy * Ww + gx];
            sg[idx] = v;
        }
        // load weight chunk, layout [c][k][o]
        for (int idx = threadIdx.x; idx < 16 * 216; idx += 256) {
            int c = idx / 216; int r = idx - c * 216;
            int k = r / 24;    int o = r - k * 24;
            sw[idx] = wgt[((size_t)o * CH_G + cc * 16 + c) * 9 + k];
        }
        __syncthreads();

        for (int c = 0; c < 16; c++) {
            unsigned long long gd[9];
#pragma unroll
            for (int dy = 0; dy < 3; dy++)
#pragma unroll
                for (int dx = 0; dx < 3; dx++) {
                    float gv = sg[c * 340 + (ty + dy) * 34 + (tx + dx)];
                    DUP2(gd[dy * 3 + dx], gv);
                }
#pragma unroll
            for (int k = 0; k < 9; k++) {
                const ulonglong2* wv = (const ulonglong2*)&sw[(c * 9 + k) * 24];
                unsigned long long gk = gd[k];
#pragma unroll
                for (int h = 0; h < 6; h++) {
                    ulonglong2 w2 = wv[h];
                    FFMA2(acc[2 * h],     w2.x, gk, acc[2 * h]);
                    FFMA2(acc[2 * h + 1], w2.y, gk, acc[2 * h + 1]);
                }
            }
        }
    }

    int gy = by + ty, gx = bx + tx;
    size_t pix = (size_t)gy * Ww + gx;
    ulonglong2* dst = (ulonglong2*)&g_oaT[((size_t)b * HW + pix) * COUT];
#pragma unroll
    for (int h = 0; h < 6; h++)
        dst[h] = make_ulonglong2(acc[2 * h], acc[2 * h + 1]);
}

// ---------------------------------------------------------------------------
// Stage 3: deformable sampling, ONE THREAD PER SAMPLE PIXEL (all 8 n).
// Offsets: 4 contiguous LDG.128, warp-contiguous. Taps: warp = 32 consecutive
// pixels, same n per instruction -> 32B lane stride, n<4 taps mutually
// L1-resident. Stores: per channel 8 consecutive floats (all n) = 2 STG.128,
// warp-contiguous 1KB. Same g_smp layout as R6 (final_kernel unchanged).
// ---------------------------------------------------------------------------
__global__ __launch_bounds__(128) void sample_kernel() {
    int t = blockIdx.x * 128 + threadIdx.x;   // exact grid: Bq*HW
    int b = t / HW; int pix = t - b * HW;
    int i = pix / Ww; int j = pix - i * Ww;

    // 16 offset floats for this pixel (4 x LDG.128, contiguous)
    float of[16];
    {
        const float4* op = (const float4*)(g_oaT + (size_t)t * COUT);
        float4 o0 = op[0], o1 = op[1], o2 = op[2], o3 = op[3];
        of[0]  = o0.x; of[1]  = o0.y; of[2]  = o0.z; of[3]  = o0.w;
        of[4]  = o1.x; of[5]  = o1.y; of[6]  = o1.z; of[7]  = o1.w;
        of[8]  = o2.x; of[9]  = o2.y; of[10] = o2.z; of[11] = o2.w;
        of[12] = o3.x; of[13] = o3.y; of[14] = o3.z; of[15] = o3.w;
    }

    const float* fb = g_feaT + (size_t)b * HW * C_FEA;
    float fi = (float)i, fj = (float)j;

    float acc[NUM][C_FEA];   // [n][c]
#pragma unroll
    for (int n = 0; n < NUM; n++) {
        float base = (n < 4) ? fi : fj;
        float x = of[2 * n] + base;
        float y = of[2 * n + 1] + base;

        float x0 = floorf(x), y0 = floorf(y);
        float fx = x - x0, fy = y - y0;

        float a0 = 0, a1 = 0, a2 = 0, a3 = 0, a4 = 0, a5 = 0, a6 = 0, a7 = 0;
#pragma unroll
        for (int cy = 0; cy < 2; cy++)
#pragma unroll
            for (int cx = 0; cx < 2; cx++) {
                float xi = x0 + cx, yi = y0 + cy;
                float wgt = (cy ? fy : 1.f - fy) * (cx ? fx : 1.f - fx);
                if (xi >= 0.f && xi <= (float)(Ww - 1) && yi >= 0.f && yi <= (float)(Hh - 1)) {
                    const float4* v = (const float4*)(fb + ((size_t)((int)yi * Ww + (int)xi)) * C_FEA);
                    float4 v0 = v[0], v1 = v[1];
                    a0 += wgt * v0.x; a1 += wgt * v0.y; a2 += wgt * v0.z; a3 += wgt * v0.w;
                    a4 += wgt * v1.x; a5 += wgt * v1.y; a6 += wgt * v1.z; a7 += wgt * v1.w;
                }
            }
        acc[n][0] = a0; acc[n][1] = a1; acc[n][2] = a2; acc[n][3] = a3;
        acc[n][4] = a4; acc[n][5] = a5; acc[n][6] = a6; acc[n][7] = a7;
    }

    // stores: channel c gets 8 consecutive floats at p = pix*8 (.. +7)
    float* sb = g_smp + (size_t)b * C_FEA * Pn + (size_t)pix * 8;
#pragma unroll
    for (int c = 0; c < C_FEA; c++) {
        float4* d = (float4*)(sb + (size_t)c * Pn);
        d[0] = make_float4(acc[0][c], acc[1][c], acc[2][c], acc[3][c]);
        d[1] = make_float4(acc[4][c], acc[5][c], acc[6][c], acc[7][c]);
    }
}

// single-channel bilinear with zero padding (reference _bilinear_zeros)
__device__ __forceinline__ float bil1(const float* __restrict__ img, float x, float y) {
    float x0 = floorf(x), y0 = floorf(y);
    float fx = x - x0, fy = y - y0;
    float r = 0.f;
#pragma unroll
    for (int cy = 0; cy < 2; cy++) {
#pragma unroll
        for (int cx = 0; cx < 2; cx++) {
            float xi = x0 + cx, yi = y0 + cy;
            if (xi >= 0.f && xi <= (float)(Ww - 1) && yi >= 0.f && yi <= (float)(Hh - 1)) {
                float wgt = (cy ? fy : 1.f - fy) * (cx ? fx : 1.f - fx);
                r += wgt * img[(int)yi * Ww + (int)xi];
            }
        }
    }
    return r;
}

// ---------------------------------------------------------------------------
// Stage 4: fused epilogue (exact R6 structure, measured 39us). Scramble-gather:
// cos_w[c](pix) = sum_a fea[a] * g_smp[b][Q/76800][(Q%76800)*8 + c], Q=pix*8+a
// (reads 64 consecutive floats per pixel -> warp-contiguous 8KB). TGASS tanh,
// confidence bilinear, abs-sum clamp normalize, ref insert, softmax, outputs.
// ---------------------------------------------------------------------------
__global__ void final_kernel(const float* __restrict__ gt,
                             const float* __restrict__ ascp,
                             float* __restrict__ out) {
    int t = blockIdx.x * 256 + threadIdx.x;
    if (t >= Bq * HW) return;
    int b = t / HW; int pix = t - b * HW;
    int i = pix / Ww; int j = pix - i * Ww;

    float o[COUT];
    {
        const float4* ov = (const float4*)&g_oaT[(size_t)t * COUT];
#pragma unroll
        for (int h = 0; h < 6; h++) {
            float4 v = ov[h];
            o[4 * h + 0] = v.x; o[4 * h + 1] = v.y;
            o[4 * h + 2] = v.z; o[4 * h + 3] = v.w;
        }
    }

    const float4* fv = (const float4*)&g_feaT[(size_t)t * C_FEA];
    float4 f0 = fv[0], f1 = fv[1];
    float fea[8] = {f0.x, f0.y, f0.z, f0.w, f1.x, f1.y, f1.z, f1.w};

    float cw0 = 0, cw1 = 0, cw2 = 0, cw3 = 0, cw4 = 0, cw5 = 0, cw6 = 0, cw7 = 0;
#pragma unroll
    for (int a = 0; a < 8; a++) {
        int Q  = pix * 8 + a;
        int ch = Q / HW;
        int p2 = Q - ch * HW;
        const float4* sp = (const float4*)&g_smp[((size_t)(b * C_FEA + ch)) * Pn + (size_t)p2 * 8];
        float4 s0 = sp[0], s1 = sp[1];
        float fa = fea[a];
        cw0 += fa * s0.x; cw1 += fa * s0.y; cw2 += fa * s0.z; cw3 += fa * s0.w;
        cw4 += fa * s1.x; cw5 += fa * s1.y; cw6 += fa * s1.z; cw7 += fa * s1.w;
    }
    float cosw[8] = {cw0, cw1, cw2, cw3, cw4, cw5, cw6, cw7};

    float denom = ascp[0] + 1e-8f;
    const float* gb = gt + (size_t)b * HW;

    float aff[8];
#pragma unroll
    for (int n = 0; n < 8; n++) {
        float a0 = tanhf(o[16 + n] * cosw[n]) / denom;
        float y = o[2 * n]     + (float)i;   // channel 0 = dy
        float x = o[2 * n + 1] + (float)j;   // channel 1 = dx
        aff[n] = a0 * bil1(gb, x, y);
    }

    float sabs = 0.f;
#pragma unroll
    for (int n = 0; n < 8; n++) sabs += fabsf(aff[n]);
    sabs += 1e-4f;
    sabs = fmaxf(sabs, 1.0f);

    float ssum = 0.f;
#pragma unroll
    for (int n = 0; n < 8; n++) { aff[n] = aff[n] / sabs; ssum += aff[n]; }

    float v[9];
    v[0] = aff[0]; v[1] = aff[1]; v[2] = aff[2]; v[3] = aff[3];
    v[4] = 1.0f - ssum;
    v[5] = aff[4]; v[6] = aff[5]; v[7] = aff[6]; v[8] = aff[7];

    float m = v[0];
#pragma unroll
    for (int k = 1; k < 9; k++) m = fmaxf(m, v[k]);
    float e[9], es = 0.f;
#pragma unroll
    for (int k = 0; k < 9; k++) { e[k] = expf(v[k] - m); es += e[k]; }
    float inv = 1.0f / es;

    // output: offset_full (B,18,H,W) flattened, then aff_full (B,9,H,W)
    const size_t OFFA = (size_t)Bq * 18 * HW;
#pragma unroll
    for (int k = 0; k < 8; k++)
        out[((size_t)(b * 18 + k)) * HW + pix] = o[k];
    out[((size_t)(b * 18 + 8)) * HW + pix] = 0.f;
    out[((size_t)(b * 18 + 9)) * HW + pix] = 0.f;
#pragma unroll
    for (int k = 10; k < 18; k++)
        out[((size_t)(b * 18 + k)) * HW + pix] = o[k - 2];
#pragma unroll
    for (int k = 0; k < 9; k++)
        out[OFFA + ((size_t)(b * 9 + k)) * HW + pix] = e[k] * inv;
}

// ---------------------------------------------------------------------------
extern "C" void kernel_launch(void* const* d_in, const int* in_sizes, int n_in,
                              void* d_out, int out_size) {
    const float* guidance = (const float*)d_in[0];
    const float* gt       = (const float*)d_in[1];
    const float* fea      = (const float*)d_in[2];
    const float* conv_w   = (const float*)d_in[3];
    const float* conv_b   = (const float*)d_in[4];
    const float* asc      = (const float*)d_in[5];
    float* out = (float*)d_out;

    upsample_kernel<<<(Bq * HW + 255) / 256, 256>>>(fea);

    dim3 cg(Ww / 32, Hh / 8, Bq);   // 10 x 30 x 4 = 1200 blocks, 256 threads
    conv_kernel<<<cg, 256>>>(guidance, conv_w, conv_b);

    sample_kernel<<<(Bq * HW) / 128, 128>>>();   // 2400 blocks exact

    final_kernel<<<(Bq * HW + 255) / 256, 256>>>(gt, asc, out);
}